// round 11
// baseline (speedup 1.0000x reference)
#include <cuda_runtime.h>
#include <cuda_fp16.h>
#include <cstdint>
#include <cstddef>

// ============================ problem constants ============================
static constexpr int K_FEAT = 4096;   // in_features (K)
static constexpr int N_FEAT = 4096;   // out_features (N)
static constexpr int M_ROWS = 8192;   // 4 * 2048 (M)

static constexpr int TILE_M = 128;
static constexpr int TILE_N = 256;
static constexpr int TILE_K = 32;                  // halves per stage row
static constexpr int STAGES = 4;
static constexpr int KT     = K_FEAT / TILE_K;     // 128 k-iterations

// SMEM stage layout: padded rows of 32 halves -> 80 bytes (64 data + 16 pad)
static constexpr int ROW_BYTES = 80;
static constexpr int A_STAGE   = TILE_M * ROW_BYTES;            // 10240
static constexpr int B_STAGE   = TILE_N * ROW_BYTES;            // 20480
static constexpr int STAGE_BYTES = A_STAGE + B_STAGE;           // 30720
static constexpr int SMEM_BYTES  = STAGES * STAGE_BYTES;        // 122880

// ============================ scratch (no cudaMalloc allowed) ==============
__device__ __align__(16) __half g_x_f16[(size_t)M_ROWS * K_FEAT];  // 64 MB
__device__ __align__(16) __half g_w_f16[(size_t)N_FEAT * K_FEAT];  // 32 MB

// ============================ PTX helpers ==================================
__device__ __forceinline__ unsigned smem_u32(const void* p) {
    unsigned a;
    asm("{ .reg .u64 t; cvta.to.shared.u64 t, %1; cvt.u32.u64 %0, t; }" : "=r"(a) : "l"(p));
    return a;
}
__device__ __forceinline__ void cp_async16(unsigned dst, const void* src) {
    asm volatile("cp.async.cg.shared.global [%0], [%1], 16;"
                 :: "r"(dst), "l"(__cvta_generic_to_global(src)));
}
#define CP_COMMIT() asm volatile("cp.async.commit_group;" ::: "memory")
#define CP_WAIT2()  asm volatile("cp.async.wait_group 2;" ::: "memory")
#define CP_WAIT0()  asm volatile("cp.async.wait_group 0;" ::: "memory")

__device__ __forceinline__ void ldsm_x4(unsigned& r0, unsigned& r1, unsigned& r2, unsigned& r3,
                                        unsigned addr) {
    asm volatile("ldmatrix.sync.aligned.m8n8.x4.shared.b16 {%0,%1,%2,%3}, [%4];"
                 : "=r"(r0), "=r"(r1), "=r"(r2), "=r"(r3) : "r"(addr));
}
__device__ __forceinline__ void mma_16816(float* c, unsigned a0, unsigned a1, unsigned a2,
                                          unsigned a3, unsigned b0, unsigned b1) {
    asm volatile(
        "mma.sync.aligned.m16n8k16.row.col.f32.f16.f16.f32 "
        "{%0,%1,%2,%3}, {%4,%5,%6,%7}, {%8,%9}, {%0,%1,%2,%3};"
        : "+f"(c[0]), "+f"(c[1]), "+f"(c[2]), "+f"(c[3])
        : "r"(a0), "r"(a1), "r"(a2), "r"(a3), "r"(b0), "r"(b1));
}

// ============================ fused prologue ===============================
__global__ void prologue_kernel(const float4* __restrict__ x, int n4,
                                const int* __restrict__ wp,
                                const float* __restrict__ params, int npk) {
    const int stride = gridDim.x * blockDim.x;
    uint2* __restrict__ xo = reinterpret_cast<uint2*>(g_x_f16);
    for (int i = blockIdx.x * blockDim.x + threadIdx.x; i < n4; i += stride) {
        float4 v = x[i];
        __half2 a = __floats2half2_rn(v.x, v.y);
        __half2 b = __floats2half2_rn(v.z, v.w);
        uint2 u;
        u.x = *reinterpret_cast<const unsigned*>(&a);
        u.y = *reinterpret_cast<const unsigned*>(&b);
        xo[i] = u;
    }
    __half2* __restrict__ wo = reinterpret_cast<__half2*>(g_w_f16);
    for (int i = blockIdx.x * blockDim.x + threadIdx.x; i < npk; i += stride) {
        int g = i >> 7;                     // 128 packed int32 per group of 256 values
        float s = params[2 * g];
        float z = params[2 * g + 1];
        int p = wp[i];
        float lo = (float)(p & 15);
        float hi = (float)((p >> 4) & 15);
        wo[i] = __floats2half2_rn(fmaf(lo, s, z), fmaf(hi, s, z));
    }
}

// ============================ GEMM kernel ==================================
// CTA: 128x256, K staged 32. 256 threads = 8 warps, warp grid 2(M) x 4(N),
// warp tile 64x64 (128 B of LDSM traffic per MMA vs 192 for 64x32).
// Fragments double-buffered across the two k16 steps: step-1 LDSMs issued
// before step-0's MMA chain so MMA execution hides LDSM latency (the R9
// failure mode at 8 warps). Pipeline skeleton identical to the 772us R5.
__global__ void __launch_bounds__(256) gemm_f16_kernel(float* __restrict__ out) {
    extern __shared__ __align__(128) char smem[];
    const unsigned sb = smem_u32(smem);
    const int tid  = threadIdx.x;
    const int wid  = tid >> 5;
    const int lane = tid & 31;
    const int warp_m = wid & 1;      // 0..1
    const int warp_n = wid >> 1;     // 0..3
    const int ntile = blockIdx.x;    // 16 tiles of 256
    const int mtile = blockIdx.y;    // 64 tiles of 128

    const char* aG = reinterpret_cast<const char*>(g_x_f16)
                   + (size_t)(mtile * TILE_M) * (K_FEAT * 2);
    const char* bG = reinterpret_cast<const char*>(g_w_f16)
                   + (size_t)(ntile * TILE_N) * (K_FEAT * 2);

    // ---- per-thread cp.async assignments (6 x 16B chunks per thread) ----
    auto load_stage = [&](int kt, int buf) {
        const unsigned stage = sb + buf * STAGE_BYTES;
        const char* aS = aG + (size_t)kt * (TILE_K * 2);
        const char* bS = bG + (size_t)kt * (TILE_K * 2);
        #pragma unroll
        for (int i = 0; i < 2; ++i) {         // A: 512 chunks
            int idx = tid + i * 256;
            int r = idx >> 2, c = idx & 3;
            cp_async16(stage + r * ROW_BYTES + c * 16,
                       aS + (size_t)r * (K_FEAT * 2) + c * 16);
        }
        #pragma unroll
        for (int i = 0; i < 4; ++i) {         // B: 1024 chunks
            int idx = tid + i * 256;
            int r = idx >> 2, c = idx & 3;
            cp_async16(stage + A_STAGE + r * ROW_BYTES + c * 16,
                       bS + (size_t)r * (K_FEAT * 2) + c * 16);
        }
    };

    // ---- ldmatrix per-thread base offsets ----
    unsigned aOff[4];
    #pragma unroll
    for (int mt = 0; mt < 4; ++mt)
        aOff[mt] = (unsigned)((warp_m * 64 + mt * 16 + (lane & 15)) * ROW_BYTES
                              + (lane >> 4) * 16);
    unsigned bOff[4];
    #pragma unroll
    for (int nt2 = 0; nt2 < 4; ++nt2)
        bOff[nt2] = (unsigned)((warp_n * 64 + nt2 * 16 + ((lane >> 1) & 8) + (lane & 7)) * ROW_BYTES
                               + ((lane >> 3) & 1) * 16);

    float c[4][8][4];
    #pragma unroll
    for (int i = 0; i < 4; ++i)
        #pragma unroll
        for (int j = 0; j < 8; ++j)
            #pragma unroll
            for (int v = 0; v < 4; ++v) c[i][j][v] = 0.0f;

    // ---- pipeline prologue ----
    #pragma unroll
    for (int s = 0; s < STAGES - 1; ++s) { load_stage(s, s); CP_COMMIT(); }

    // ---- mainloop (R5 skeleton: wait, sync, compute, sync, load) ----
    #pragma unroll 1
    for (int kt = 0; kt < KT; ++kt) {
        const int buf = kt & (STAGES - 1);
        CP_WAIT2();
        __syncthreads();

        const unsigned aBase = sb + buf * STAGE_BYTES;
        const unsigned bBase = aBase + A_STAGE;

        unsigned a[2][4][4];
        unsigned b[2][8][2];

        // fragments for step 0
        #pragma unroll
        for (int mt = 0; mt < 4; ++mt)
            ldsm_x4(a[0][mt][0], a[0][mt][1], a[0][mt][2], a[0][mt][3], aBase + aOff[mt]);
        #pragma unroll
        for (int nt2 = 0; nt2 < 4; ++nt2) {
            unsigned r0, r1, r2, r3;
            ldsm_x4(r0, r1, r2, r3, bBase + bOff[nt2]);
            b[0][2 * nt2][0] = r0;     b[0][2 * nt2][1] = r1;
            b[0][2 * nt2 + 1][0] = r2; b[0][2 * nt2 + 1][1] = r3;
        }
        // prefetch fragments for step 1 (latency hidden by step-0 MMAs)
        #pragma unroll
        for (int mt = 0; mt < 4; ++mt)
            ldsm_x4(a[1][mt][0], a[1][mt][1], a[1][mt][2], a[1][mt][3], aBase + aOff[mt] + 32);
        #pragma unroll
        for (int nt2 = 0; nt2 < 4; ++nt2) {
            unsigned r0, r1, r2, r3;
            ldsm_x4(r0, r1, r2, r3, bBase + bOff[nt2] + 32);
            b[1][2 * nt2][0] = r0;     b[1][2 * nt2][1] = r1;
            b[1][2 * nt2 + 1][0] = r2; b[1][2 * nt2 + 1][1] = r3;
        }

        #pragma unroll
        for (int s = 0; s < 2; ++s)
            #pragma unroll
            for (int mt = 0; mt < 4; ++mt)
                #pragma unroll
                for (int nt = 0; nt < 8; ++nt)
                    mma_16816(c[mt][nt], a[s][mt][0], a[s][mt][1], a[s][mt][2], a[s][mt][3],
                              b[s][nt][0], b[s][nt][1]);

        __syncthreads();                 // all warps done reading buf before reuse
        const int pf = kt + STAGES - 1;
        if (pf < KT) load_stage(pf, pf & (STAGES - 1));
        CP_COMMIT();                     // commit every iter (possibly empty group)
    }
    CP_WAIT0();

    // ---- epilogue: direct fp32 stores ----
    const int mwbase = mtile * TILE_M + warp_m * 64;
    const int nwbase = ntile * TILE_N + warp_n * 64;
    const int qrow = lane >> 2;          // 0..7
    const int qcol = (lane & 3) * 2;     // 0,2,4,6
    #pragma unroll
    for (int mt = 0; mt < 4; ++mt) {
        #pragma unroll
        for (int nt = 0; nt < 8; ++nt) {
            const int m0 = mwbase + mt * 16 + qrow;
            const int n0 = nwbase + nt * 8 + qcol;
            float2 v0 = make_float2(c[mt][nt][0], c[mt][nt][1]);
            float2 v1 = make_float2(c[mt][nt][2], c[mt][nt][3]);
            *reinterpret_cast<float2*>(out + (size_t)m0 * N_FEAT + n0) = v0;
            *reinterpret_cast<float2*>(out + (size_t)(m0 + 8) * N_FEAT + n0) = v1;
        }
    }
}

// ============================ launch =======================================
extern "C" void kernel_launch(void* const* d_in, const int* in_sizes, int n_in,
                              void* d_out, int out_size) {
    const float* x       = (const float*)d_in[0];
    const int*   wpacked = (const int*)d_in[1];
    const float* wparams = (const float*)d_in[2];
    float* out = (float*)d_out;

    cudaFuncSetAttribute(gemm_f16_kernel, cudaFuncAttributeMaxDynamicSharedMemorySize,
                         SMEM_BYTES);

    const int n4  = (M_ROWS * K_FEAT) / 4;         // 8,388,608 float4s
    const int npk = (N_FEAT * K_FEAT) / 2;         // 8,388,608 packed int32s
    prologue_kernel<<<4096, 256>>>(reinterpret_cast<const float4*>(x), n4,
                                   wpacked, wparams, npk);

    dim3 grid(N_FEAT / TILE_N, M_ROWS / TILE_M);   // (16, 64)
    gemm_f16_kernel<<<grid, 256, SMEM_BYTES>>>(out);
}

// round 12
// speedup vs baseline: 1.9429x; 1.9429x over previous
#include <cuda_runtime.h>
#include <cuda_fp16.h>
#include <cstdint>
#include <cstddef>

// ============================ problem constants ============================
static constexpr int K_FEAT = 4096;   // in_features (K)
static constexpr int N_FEAT = 4096;   // out_features (N)
static constexpr int M_ROWS = 8192;   // 4 * 2048 (M)

static constexpr int TILE_M = 128;
static constexpr int TILE_N = 256;
static constexpr int TILE_K = 32;                  // halves per stage row
static constexpr int STAGES = 4;
static constexpr int KT     = K_FEAT / TILE_K;     // 128 k-iterations

// SMEM stage layout: padded rows of 32 halves -> 80 bytes (64 data + 16 pad)
static constexpr int ROW_BYTES = 80;
static constexpr int A_STAGE   = TILE_M * ROW_BYTES;            // 10240
static constexpr int B_STAGE   = TILE_N * ROW_BYTES;            // 20480
static constexpr int STAGE_BYTES = A_STAGE + B_STAGE;           // 30720
static constexpr int SMEM_BYTES  = STAGES * STAGE_BYTES;        // 122880

// ============================ scratch (no cudaMalloc allowed) ==============
__device__ __align__(16) __half g_x_f16[(size_t)M_ROWS * K_FEAT];  // 64 MB
__device__ __align__(16) __half g_w_f16[(size_t)N_FEAT * K_FEAT];  // 32 MB

// ============================ PTX helpers ==================================
__device__ __forceinline__ unsigned smem_u32(const void* p) {
    unsigned a;
    asm("{ .reg .u64 t; cvta.to.shared.u64 t, %1; cvt.u32.u64 %0, t; }" : "=r"(a) : "l"(p));
    return a;
}
__device__ __forceinline__ void cp_async16(unsigned dst, const void* src) {
    asm volatile("cp.async.cg.shared.global [%0], [%1], 16;"
                 :: "r"(dst), "l"(__cvta_generic_to_global(src)));
}
#define CP_COMMIT() asm volatile("cp.async.commit_group;" ::: "memory")
#define CP_WAIT2()  asm volatile("cp.async.wait_group 2;" ::: "memory")
#define CP_WAIT0()  asm volatile("cp.async.wait_group 0;" ::: "memory")

__device__ __forceinline__ void ldsm_x4(unsigned& r0, unsigned& r1, unsigned& r2, unsigned& r3,
                                        unsigned addr) {
    asm volatile("ldmatrix.sync.aligned.m8n8.x4.shared.b16 {%0,%1,%2,%3}, [%4];"
                 : "=r"(r0), "=r"(r1), "=r"(r2), "=r"(r3) : "r"(addr));
}
__device__ __forceinline__ void mma_16816(float* c, unsigned a0, unsigned a1, unsigned a2,
                                          unsigned a3, unsigned b0, unsigned b1) {
    asm volatile(
        "mma.sync.aligned.m16n8k16.row.col.f32.f16.f16.f32 "
        "{%0,%1,%2,%3}, {%4,%5,%6,%7}, {%8,%9}, {%0,%1,%2,%3};"
        : "+f"(c[0]), "+f"(c[1]), "+f"(c[2]), "+f"(c[3])
        : "r"(a0), "r"(a1), "r"(a2), "r"(a3), "r"(b0), "r"(b1));
}

// ============================ fused prologue ===============================
// One launch: fp32 x -> fp16 (DRAM-bound), then 4-bit W -> fp16 (DRAM-bound).
__global__ void prologue_kernel(const float4* __restrict__ x, int n4,
                                const int* __restrict__ wp,
                                const float* __restrict__ params, int npk) {
    const int stride = gridDim.x * blockDim.x;
    const int t0 = blockIdx.x * blockDim.x + threadIdx.x;
    uint2* __restrict__ xo = reinterpret_cast<uint2*>(g_x_f16);
    for (int i = t0; i < n4; i += stride) {
        float4 v = x[i];
        __half2 a = __floats2half2_rn(v.x, v.y);
        __half2 b = __floats2half2_rn(v.z, v.w);
        uint2 u;
        u.x = *reinterpret_cast<const unsigned*>(&a);
        u.y = *reinterpret_cast<const unsigned*>(&b);
        xo[i] = u;
    }
    __half2* __restrict__ wo = reinterpret_cast<__half2*>(g_w_f16);
    for (int i = t0; i < npk; i += stride) {
        int g = i >> 7;                     // 128 packed int32 per group of 256 values
        float s = params[2 * g];
        float z = params[2 * g + 1];
        int p = wp[i];
        float lo = (float)(p & 15);
        float hi = (float)((p >> 4) & 15);
        wo[i] = __floats2half2_rn(fmaf(lo, s, z), fmaf(hi, s, z));
    }
}

// ============================ GEMM kernel (R5 verbatim) ====================
// CTA: 128x256x(K staged 32). 512 threads = 16 warps, warp grid 2(M) x 8(N),
// warp tile 64x32. mma.sync.m16n8k16 fp16->fp32. 4-stage cp.async pipeline.
// Measured ~99% of the sm_103a mma.sync tensor-pipe ceiling — do not restructure.
__global__ void __launch_bounds__(512, 1) gemm_f16_kernel(float* __restrict__ out) {
    extern __shared__ __align__(128) char smem[];
    const unsigned sb = smem_u32(smem);
    const int tid  = threadIdx.x;
    const int wid  = tid >> 5;
    const int lane = tid & 31;
    const int warp_m = wid & 1;      // 0..1
    const int warp_n = wid >> 1;     // 0..7
    const int ntile = blockIdx.x;    // 16 tiles of 256
    const int mtile = blockIdx.y;    // 64 tiles of 128

    const char* aG = reinterpret_cast<const char*>(g_x_f16)
                   + (size_t)(mtile * TILE_M) * (K_FEAT * 2);
    const char* bG = reinterpret_cast<const char*>(g_w_f16)
                   + (size_t)(ntile * TILE_N) * (K_FEAT * 2);

    // ---- per-thread cp.async assignments (3 x 16B chunks per thread) ----
    auto load_stage = [&](int kt, int buf) {
        const unsigned stage = sb + buf * STAGE_BYTES;
        {   // A chunk
            int idx = tid;                    // 0..511
            int r = idx >> 2, c = idx & 3;
            cp_async16(stage + r * ROW_BYTES + c * 16,
                       aG + (size_t)r * (K_FEAT * 2) + (size_t)kt * (TILE_K * 2) + c * 16);
        }
        #pragma unroll
        for (int i = 0; i < 2; ++i) {         // B chunks
            int idx = tid + i * 512;          // 0..1023
            int r = idx >> 2, c = idx & 3;
            cp_async16(stage + A_STAGE + r * ROW_BYTES + c * 16,
                       bG + (size_t)r * (K_FEAT * 2) + (size_t)kt * (TILE_K * 2) + c * 16);
        }
    };

    // ---- ldmatrix per-thread base offsets ----
    unsigned aOff[4];
    #pragma unroll
    for (int mt = 0; mt < 4; ++mt)
        aOff[mt] = (unsigned)((warp_m * 64 + mt * 16 + (lane & 15)) * ROW_BYTES
                              + (lane >> 4) * 16);
    unsigned bOff[2];
    #pragma unroll
    for (int nt2 = 0; nt2 < 2; ++nt2)
        bOff[nt2] = (unsigned)((warp_n * 32 + nt2 * 16 + ((lane >> 1) & 8) + (lane & 7)) * ROW_BYTES
                               + ((lane >> 3) & 1) * 16);

    float c[4][4][4];
    #pragma unroll
    for (int i = 0; i < 4; ++i)
        #pragma unroll
        for (int j = 0; j < 4; ++j)
            #pragma unroll
            for (int v = 0; v < 4; ++v) c[i][j][v] = 0.0f;

    // ---- pipeline prologue ----
    #pragma unroll
    for (int s = 0; s < STAGES - 1; ++s) { load_stage(s, s); CP_COMMIT(); }

    // ---- mainloop ----
    #pragma unroll 1
    for (int kt = 0; kt < KT; ++kt) {
        const int buf = kt & (STAGES - 1);
        CP_WAIT2();
        __syncthreads();

        const unsigned aBase = sb + buf * STAGE_BYTES;
        const unsigned bBase = aBase + A_STAGE;

        #pragma unroll
        for (int s = 0; s < 2; ++s) {                 // two k16 steps
            const unsigned ks = (unsigned)(s * 32);   // 16 halves = 32 bytes
            unsigned a[4][4];
            #pragma unroll
            for (int mt = 0; mt < 4; ++mt)
                ldsm_x4(a[mt][0], a[mt][1], a[mt][2], a[mt][3], aBase + aOff[mt] + ks);
            unsigned b[4][2];
            #pragma unroll
            for (int nt2 = 0; nt2 < 2; ++nt2) {
                unsigned r0, r1, r2, r3;
                ldsm_x4(r0, r1, r2, r3, bBase + bOff[nt2] + ks);
                b[2 * nt2][0] = r0; b[2 * nt2][1] = r1;
                b[2 * nt2 + 1][0] = r2; b[2 * nt2 + 1][1] = r3;
            }
            #pragma unroll
            for (int mt = 0; mt < 4; ++mt)
                #pragma unroll
                for (int nt = 0; nt < 4; ++nt)
                    mma_16816(c[mt][nt], a[mt][0], a[mt][1], a[mt][2], a[mt][3],
                              b[nt][0], b[nt][1]);
        }

        __syncthreads();                 // all warps done reading buf before reuse
        const int pf = kt + STAGES - 1;
        if (pf < KT) load_stage(pf, pf & (STAGES - 1));
        CP_COMMIT();                     // commit every iter (possibly empty group)
    }
    CP_WAIT0();

    // ---- epilogue: direct fp32 stores ----
    const int mwbase = mtile * TILE_M + warp_m * 64;
    const int nwbase = ntile * TILE_N + warp_n * 32;
    const int qrow = lane >> 2;          // 0..7
    const int qcol = (lane & 3) * 2;     // 0,2,4,6
    #pragma unroll
    for (int mt = 0; mt < 4; ++mt) {
        #pragma unroll
        for (int nt = 0; nt < 4; ++nt) {
            const int m0 = mwbase + mt * 16 + qrow;
            const int n0 = nwbase + nt * 8 + qcol;
            float2 v0 = make_float2(c[mt][nt][0], c[mt][nt][1]);
            float2 v1 = make_float2(c[mt][nt][2], c[mt][nt][3]);
            *reinterpret_cast<float2*>(out + (size_t)m0 * N_FEAT + n0) = v0;
            *reinterpret_cast<float2*>(out + (size_t)(m0 + 8) * N_FEAT + n0) = v1;
        }
    }
}

// ============================ launch =======================================
extern "C" void kernel_launch(void* const* d_in, const int* in_sizes, int n_in,
                              void* d_out, int out_size) {
    const float* x       = (const float*)d_in[0];
    const int*   wpacked = (const int*)d_in[1];
    const float* wparams = (const float*)d_in[2];
    float* out = (float*)d_out;

    cudaFuncSetAttribute(gemm_f16_kernel, cudaFuncAttributeMaxDynamicSharedMemorySize,
                         SMEM_BYTES);

    const int n4  = (M_ROWS * K_FEAT) / 4;         // 8,388,608 float4s
    const int npk = (N_FEAT * K_FEAT) / 2;         // 8,388,608 packed int32s
    prologue_kernel<<<4096, 256>>>(reinterpret_cast<const float4*>(x), n4,
                                   wpacked, wparams, npk);

    dim3 grid(N_FEAT / TILE_N, M_ROWS / TILE_M);   // (16, 64)
    gemm_f16_kernel<<<grid, 512, SMEM_BYTES>>>(out);
}

// round 13
// speedup vs baseline: 2.0141x; 1.0366x over previous
#include <cuda_runtime.h>
#include <cuda_fp16.h>
#include <cstdint>
#include <cstddef>

// ============================ problem constants ============================
static constexpr int K_FEAT = 4096;   // in_features (K)
static constexpr int N_FEAT = 4096;   // out_features (N)
static constexpr int M_ROWS = 8192;   // 4 * 2048 (M)

static constexpr int TILE_M = 128;
static constexpr int TILE_N = 256;
static constexpr int TILE_K = 32;                  // halves per stage row
static constexpr int STAGES = 4;
static constexpr int KT     = K_FEAT / TILE_K;     // 128 k-iterations

// SMEM stage layout: padded rows of 32 halves -> 80 bytes (64 data + 16 pad)
static constexpr int ROW_BYTES = 80;
static constexpr int A_STAGE   = TILE_M * ROW_BYTES;            // 10240
static constexpr int B_STAGE   = TILE_N * ROW_BYTES;            // 20480
static constexpr int STAGE_BYTES = A_STAGE + B_STAGE;           // 30720
static constexpr int SMEM_BYTES  = STAGES * STAGE_BYTES;        // 122880

// ============================ scratch (no cudaMalloc allowed) ==============
__device__ __align__(16) __half g_x_f16[(size_t)M_ROWS * K_FEAT];  // 64 MB
__device__ __align__(16) __half g_w_f16[(size_t)N_FEAT * K_FEAT];  // 32 MB

// ============================ PTX helpers ==================================
__device__ __forceinline__ unsigned smem_u32(const void* p) {
    unsigned a;
    asm("{ .reg .u64 t; cvta.to.shared.u64 t, %1; cvt.u32.u64 %0, t; }" : "=r"(a) : "l"(p));
    return a;
}
__device__ __forceinline__ void cp_async16(unsigned dst, const void* src) {
    asm volatile("cp.async.cg.shared.global [%0], [%1], 16;"
                 :: "r"(dst), "l"(__cvta_generic_to_global(src)));
}
#define CP_COMMIT() asm volatile("cp.async.commit_group;" ::: "memory")
#define CP_WAIT2()  asm volatile("cp.async.wait_group 2;" ::: "memory")
#define CP_WAIT0()  asm volatile("cp.async.wait_group 0;" ::: "memory")

__device__ __forceinline__ void ldsm_x4(unsigned& r0, unsigned& r1, unsigned& r2, unsigned& r3,
                                        unsigned addr) {
    asm volatile("ldmatrix.sync.aligned.m8n8.x4.shared.b16 {%0,%1,%2,%3}, [%4];"
                 : "=r"(r0), "=r"(r1), "=r"(r2), "=r"(r3) : "r"(addr));
}
__device__ __forceinline__ void mma_16816(float* c, unsigned a0, unsigned a1, unsigned a2,
                                          unsigned a3, unsigned b0, unsigned b1) {
    asm volatile(
        "mma.sync.aligned.m16n8k16.row.col.f32.f16.f16.f32 "
        "{%0,%1,%2,%3}, {%4,%5,%6,%7}, {%8,%9}, {%0,%1,%2,%3};"
        : "+f"(c[0]), "+f"(c[1]), "+f"(c[2]), "+f"(c[3])
        : "r"(a0), "r"(a1), "r"(a2), "r"(a3), "r"(b0), "r"(b1));
}

// ============================ fused prologue ===============================
// One launch: fp32 x -> fp16 (DRAM-bound), then 4-bit W -> fp16 (DRAM-bound).
__global__ void prologue_kernel(const float4* __restrict__ x, int n4,
                                const int* __restrict__ wp,
                                const float* __restrict__ params, int npk) {
    const int stride = gridDim.x * blockDim.x;
    const int t0 = blockIdx.x * blockDim.x + threadIdx.x;
    uint2* __restrict__ xo = reinterpret_cast<uint2*>(g_x_f16);
    for (int i = t0; i < n4; i += stride) {
        float4 v = x[i];
        __half2 a = __floats2half2_rn(v.x, v.y);
        __half2 b = __floats2half2_rn(v.z, v.w);
        uint2 u;
        u.x = *reinterpret_cast<const unsigned*>(&a);
        u.y = *reinterpret_cast<const unsigned*>(&b);
        xo[i] = u;
    }
    __half2* __restrict__ wo = reinterpret_cast<__half2*>(g_w_f16);
    for (int i = t0; i < npk; i += stride) {
        int g = i >> 7;                     // 128 packed int32 per group of 256 values
        float s = params[2 * g];
        float z = params[2 * g + 1];
        int p = wp[i];
        float lo = (float)(p & 15);
        float hi = (float)((p >> 4) & 15);
        wo[i] = __floats2half2_rn(fmaf(lo, s, z), fmaf(hi, s, z));
    }
}

// ============================ GEMM kernel ==================================
// CTA: 128x256x(K staged 32). 512 threads = 16 warps, warp grid 2(M) x 8(N),
// warp tile 64x32. mma.sync.m16n8k16 fp16->fp32. 4-stage cp.async pipeline.
// SINGLE __syncthreads per iteration: the post-compute barrier is redundant —
// loads at iter kt target buffer (kt-1)%4, whose readers (compute(kt-1)) are
// already ordered before these loads by bar1(kt). Otherwise identical to the
// 766.6us R12 kernel.
__global__ void __launch_bounds__(512, 1) gemm_f16_kernel(float* __restrict__ out) {
    extern __shared__ __align__(128) char smem[];
    const unsigned sb = smem_u32(smem);
    const int tid  = threadIdx.x;
    const int wid  = tid >> 5;
    const int lane = tid & 31;
    const int warp_m = wid & 1;      // 0..1
    const int warp_n = wid >> 1;     // 0..7
    const int ntile = blockIdx.x;    // 16 tiles of 256
    const int mtile = blockIdx.y;    // 64 tiles of 128

    const char* aG = reinterpret_cast<const char*>(g_x_f16)
                   + (size_t)(mtile * TILE_M) * (K_FEAT * 2);
    const char* bG = reinterpret_cast<const char*>(g_w_f16)
                   + (size_t)(ntile * TILE_N) * (K_FEAT * 2);

    // ---- per-thread cp.async assignments (3 x 16B chunks per thread) ----
    auto load_stage = [&](int kt, int buf) {
        const unsigned stage = sb + buf * STAGE_BYTES;
        {   // A chunk
            int idx = tid;                    // 0..511
            int r = idx >> 2, c = idx & 3;
            cp_async16(stage + r * ROW_BYTES + c * 16,
                       aG + (size_t)r * (K_FEAT * 2) + (size_t)kt * (TILE_K * 2) + c * 16);
        }
        #pragma unroll
        for (int i = 0; i < 2; ++i) {         // B chunks
            int idx = tid + i * 512;          // 0..1023
            int r = idx >> 2, c = idx & 3;
            cp_async16(stage + A_STAGE + r * ROW_BYTES + c * 16,
                       bG + (size_t)r * (K_FEAT * 2) + (size_t)kt * (TILE_K * 2) + c * 16);
        }
    };

    // ---- ldmatrix per-thread base offsets ----
    unsigned aOff[4];
    #pragma unroll
    for (int mt = 0; mt < 4; ++mt)
        aOff[mt] = (unsigned)((warp_m * 64 + mt * 16 + (lane & 15)) * ROW_BYTES
                              + (lane >> 4) * 16);
    unsigned bOff[2];
    #pragma unroll
    for (int nt2 = 0; nt2 < 2; ++nt2)
        bOff[nt2] = (unsigned)((warp_n * 32 + nt2 * 16 + ((lane >> 1) & 8) + (lane & 7)) * ROW_BYTES
                               + ((lane >> 3) & 1) * 16);

    float c[4][4][4];
    #pragma unroll
    for (int i = 0; i < 4; ++i)
        #pragma unroll
        for (int j = 0; j < 4; ++j)
            #pragma unroll
            for (int v = 0; v < 4; ++v) c[i][j][v] = 0.0f;

    // ---- pipeline prologue ----
    #pragma unroll
    for (int s = 0; s < STAGES - 1; ++s) { load_stage(s, s); CP_COMMIT(); }

    // ---- mainloop: wait, bar, compute, load (no second barrier) ----
    #pragma unroll 1
    for (int kt = 0; kt < KT; ++kt) {
        const int buf = kt & (STAGES - 1);
        CP_WAIT2();
        __syncthreads();

        const unsigned aBase = sb + buf * STAGE_BYTES;
        const unsigned bBase = aBase + A_STAGE;

        #pragma unroll
        for (int s = 0; s < 2; ++s) {                 // two k16 steps
            const unsigned ks = (unsigned)(s * 32);   // 16 halves = 32 bytes
            unsigned a[4][4];
            #pragma unroll
            for (int mt = 0; mt < 4; ++mt)
                ldsm_x4(a[mt][0], a[mt][1], a[mt][2], a[mt][3], aBase + aOff[mt] + ks);
            unsigned b[4][2];
            #pragma unroll
            for (int nt2 = 0; nt2 < 2; ++nt2) {
                unsigned r0, r1, r2, r3;
                ldsm_x4(r0, r1, r2, r3, bBase + bOff[nt2] + ks);
                b[2 * nt2][0] = r0; b[2 * nt2][1] = r1;
                b[2 * nt2 + 1][0] = r2; b[2 * nt2 + 1][1] = r3;
            }
            #pragma unroll
            for (int mt = 0; mt < 4; ++mt)
                #pragma unroll
                for (int nt = 0; nt < 4; ++nt)
                    mma_16816(c[mt][nt], a[mt][0], a[mt][1], a[mt][2], a[mt][3],
                              b[nt][0], b[nt][1]);
        }

        // loads in the shadow of this iteration's compute; target buffer
        // (kt+3)%4 == (kt-1)%4, whose consumption was ordered before bar1(kt).
        const int pf = kt + STAGES - 1;
        if (pf < KT) load_stage(pf, pf & (STAGES - 1));
        CP_COMMIT();                     // commit every iter (possibly empty group)
    }
    CP_WAIT0();

    // ---- epilogue: direct fp32 stores ----
    const int mwbase = mtile * TILE_M + warp_m * 64;
    const int nwbase = ntile * TILE_N + warp_n * 32;
    const int qrow = lane >> 2;          // 0..7
    const int qcol = (lane & 3) * 2;     // 0,2,4,6
    #pragma unroll
    for (int mt = 0; mt < 4; ++mt) {
        #pragma unroll
        for (int nt = 0; nt < 4; ++nt) {
            const int m0 = mwbase + mt * 16 + qrow;
            const int n0 = nwbase + nt * 8 + qcol;
            float2 v0 = make_float2(c[mt][nt][0], c[mt][nt][1]);
            float2 v1 = make_float2(c[mt][nt][2], c[mt][nt][3]);
            *reinterpret_cast<float2*>(out + (size_t)m0 * N_FEAT + n0) = v0;
            *reinterpret_cast<float2*>(out + (size_t)(m0 + 8) * N_FEAT + n0) = v1;
        }
    }
}

// ============================ launch =======================================
extern "C" void kernel_launch(void* const* d_in, const int* in_sizes, int n_in,
                              void* d_out, int out_size) {
    const float* x       = (const float*)d_in[0];
    const int*   wpacked = (const int*)d_in[1];
    const float* wparams = (const float*)d_in[2];
    float* out = (float*)d_out;

    cudaFuncSetAttribute(gemm_f16_kernel, cudaFuncAttributeMaxDynamicSharedMemorySize,
                         SMEM_BYTES);

    const int n4  = (M_ROWS * K_FEAT) / 4;         // 8,388,608 float4s
    const int npk = (N_FEAT * K_FEAT) / 2;         // 8,388,608 packed int32s
    prologue_kernel<<<4096, 256>>>(reinterpret_cast<const float4*>(x), n4,
                                   wpacked, wparams, npk);

    dim3 grid(N_FEAT / TILE_N, M_ROWS / TILE_M);   // (16, 64)
    gemm_f16_kernel<<<grid, 512, SMEM_BYTES>>>(out);
}

// round 14
// speedup vs baseline: 2.1170x; 1.0511x over previous
#include <cuda_runtime.h>
#include <cuda_fp16.h>
#include <cstdint>
#include <cstddef>

// ============================ problem constants ============================
static constexpr int K_FEAT = 4096;   // in_features (K)
static constexpr int N_FEAT = 4096;   // out_features (N)
static constexpr int M_ROWS = 8192;   // 4 * 2048 (M)

static constexpr int TILE_M = 128;
static constexpr int TILE_N = 256;
static constexpr int TILE_K = 32;                  // halves per stage row
static constexpr int STAGES = 4;
static constexpr int KT     = K_FEAT / TILE_K;     // 128 k-iterations

// SMEM stage layout: padded rows of 32 halves -> 80 bytes (64 data + 16 pad)
static constexpr int ROW_BYTES = 80;
static constexpr int A_STAGE   = TILE_M * ROW_BYTES;            // 10240
static constexpr int B_STAGE   = TILE_N * ROW_BYTES;            // 20480
static constexpr int STAGE_BYTES = A_STAGE + B_STAGE;           // 30720
static constexpr int SMEM_BYTES  = STAGES * STAGE_BYTES;        // 122880

// ============================ scratch (no cudaMalloc allowed) ==============
__device__ __align__(16) __half g_x_f16[(size_t)M_ROWS * K_FEAT];  // 64 MB
__device__ __align__(16) __half g_w_f16[(size_t)N_FEAT * K_FEAT];  // 32 MB

// ============================ PTX helpers ==================================
__device__ __forceinline__ unsigned smem_u32(const void* p) {
    unsigned a;
    asm("{ .reg .u64 t; cvta.to.shared.u64 t, %1; cvt.u32.u64 %0, t; }" : "=r"(a) : "l"(p));
    return a;
}
__device__ __forceinline__ void cp_async16(unsigned dst, const void* src) {
    asm volatile("cp.async.cg.shared.global [%0], [%1], 16;"
                 :: "r"(dst), "l"(__cvta_generic_to_global(src)));
}
#define CP_COMMIT() asm volatile("cp.async.commit_group;" ::: "memory")
#define CP_WAIT2()  asm volatile("cp.async.wait_group 2;" ::: "memory")
#define CP_WAIT0()  asm volatile("cp.async.wait_group 0;" ::: "memory")

__device__ __forceinline__ void ldsm_x4(unsigned& r0, unsigned& r1, unsigned& r2, unsigned& r3,
                                        unsigned addr) {
    asm volatile("ldmatrix.sync.aligned.m8n8.x4.shared.b16 {%0,%1,%2,%3}, [%4];"
                 : "=r"(r0), "=r"(r1), "=r"(r2), "=r"(r3) : "r"(addr));
}
__device__ __forceinline__ void mma_16816(float* c, unsigned a0, unsigned a1, unsigned a2,
                                          unsigned a3, unsigned b0, unsigned b1) {
    asm volatile(
        "mma.sync.aligned.m16n8k16.row.col.f32.f16.f16.f32 "
        "{%0,%1,%2,%3}, {%4,%5,%6,%7}, {%8,%9}, {%0,%1,%2,%3};"
        : "+f"(c[0]), "+f"(c[1]), "+f"(c[2]), "+f"(c[3])
        : "r"(a0), "r"(a1), "r"(a2), "r"(a3), "r"(b0), "r"(b1));
}

// ============================ fused prologue ===============================
// One launch: fp32 x -> fp16 (DRAM-bound), then 4-bit W -> fp16 (DRAM-bound).
__global__ void prologue_kernel(const float4* __restrict__ x, int n4,
                                const int* __restrict__ wp,
                                const float* __restrict__ params, int npk) {
    const int stride = gridDim.x * blockDim.x;
    const int t0 = blockIdx.x * blockDim.x + threadIdx.x;
    uint2* __restrict__ xo = reinterpret_cast<uint2*>(g_x_f16);
    for (int i = t0; i < n4; i += stride) {
        float4 v = x[i];
        __half2 a = __floats2half2_rn(v.x, v.y);
        __half2 b = __floats2half2_rn(v.z, v.w);
        uint2 u;
        u.x = *reinterpret_cast<const unsigned*>(&a);
        u.y = *reinterpret_cast<const unsigned*>(&b);
        xo[i] = u;
    }
    __half2* __restrict__ wo = reinterpret_cast<__half2*>(g_w_f16);
    for (int i = t0; i < npk; i += stride) {
        int g = i >> 7;                     // 128 packed int32 per group of 256 values
        float s = params[2 * g];
        float z = params[2 * g + 1];
        int p = wp[i];
        float lo = (float)(p & 15);
        float hi = (float)((p >> 4) & 15);
        wo[i] = __floats2half2_rn(fmaf(lo, s, z), fmaf(hi, s, z));
    }
}

// ============================ GEMM kernel ==================================
// CTA: 128x256x(K staged 32). 512 threads = 16 warps, warp grid 2(M) x 8(N),
// warp tile 64x32. mma.sync.m16n8k16 fp16->fp32. 4-stage cp.async pipeline,
// single __syncthreads per iteration (R13 base, 739.5us).
// NEW: warp-staggered k16 steps — even warps process steps (0,1), odd warps
// (1,0) — so at any instant half the warps are in LDSM phase and half in MMA
// phase, overlapping the smem port (~984 cyc/iter) with the tensor pipe
// (~930 cyc/iter) instead of alternating between them.
__global__ void __launch_bounds__(512, 1) gemm_f16_kernel(float* __restrict__ out) {
    extern __shared__ __align__(128) char smem[];
    const unsigned sb = smem_u32(smem);
    const int tid  = threadIdx.x;
    const int wid  = tid >> 5;
    const int lane = tid & 31;
    const int warp_m = wid & 1;      // 0..1
    const int warp_n = wid >> 1;     // 0..7
    const unsigned sflip = (unsigned)(wid & 1);   // step-order stagger
    const int ntile = blockIdx.x;    // 16 tiles of 256
    const int mtile = blockIdx.y;    // 64 tiles of 128

    const char* aG = reinterpret_cast<const char*>(g_x_f16)
                   + (size_t)(mtile * TILE_M) * (K_FEAT * 2);
    const char* bG = reinterpret_cast<const char*>(g_w_f16)
                   + (size_t)(ntile * TILE_N) * (K_FEAT * 2);

    // ---- per-thread cp.async assignments (3 x 16B chunks per thread) ----
    auto load_stage = [&](int kt, int buf) {
        const unsigned stage = sb + buf * STAGE_BYTES;
        {   // A chunk
            int idx = tid;                    // 0..511
            int r = idx >> 2, c = idx & 3;
            cp_async16(stage + r * ROW_BYTES + c * 16,
                       aG + (size_t)r * (K_FEAT * 2) + (size_t)kt * (TILE_K * 2) + c * 16);
        }
        #pragma unroll
        for (int i = 0; i < 2; ++i) {         // B chunks
            int idx = tid + i * 512;          // 0..1023
            int r = idx >> 2, c = idx & 3;
            cp_async16(stage + A_STAGE + r * ROW_BYTES + c * 16,
                       bG + (size_t)r * (K_FEAT * 2) + (size_t)kt * (TILE_K * 2) + c * 16);
        }
    };

    // ---- ldmatrix per-thread base offsets ----
    unsigned aOff[4];
    #pragma unroll
    for (int mt = 0; mt < 4; ++mt)
        aOff[mt] = (unsigned)((warp_m * 64 + mt * 16 + (lane & 15)) * ROW_BYTES
                              + (lane >> 4) * 16);
    unsigned bOff[2];
    #pragma unroll
    for (int nt2 = 0; nt2 < 2; ++nt2)
        bOff[nt2] = (unsigned)((warp_n * 32 + nt2 * 16 + ((lane >> 1) & 8) + (lane & 7)) * ROW_BYTES
                               + ((lane >> 3) & 1) * 16);

    float c[4][4][4];
    #pragma unroll
    for (int i = 0; i < 4; ++i)
        #pragma unroll
        for (int j = 0; j < 4; ++j)
            #pragma unroll
            for (int v = 0; v < 4; ++v) c[i][j][v] = 0.0f;

    // ---- pipeline prologue ----
    #pragma unroll
    for (int s = 0; s < STAGES - 1; ++s) { load_stage(s, s); CP_COMMIT(); }

    // ---- mainloop: wait, bar, compute (staggered steps), load ----
    #pragma unroll 1
    for (int kt = 0; kt < KT; ++kt) {
        const int buf = kt & (STAGES - 1);
        CP_WAIT2();
        __syncthreads();

        const unsigned aBase = sb + buf * STAGE_BYTES;
        const unsigned bBase = aBase + A_STAGE;

        #pragma unroll
        for (int s = 0; s < 2; ++s) {                 // two k16 steps, staggered
            const unsigned ks = ((unsigned)s ^ sflip) * 32;   // 16 halves = 32 bytes
            unsigned a[4][4];
            #pragma unroll
            for (int mt = 0; mt < 4; ++mt)
                ldsm_x4(a[mt][0], a[mt][1], a[mt][2], a[mt][3], aBase + aOff[mt] + ks);
            unsigned b[4][2];
            #pragma unroll
            for (int nt2 = 0; nt2 < 2; ++nt2) {
                unsigned r0, r1, r2, r3;
                ldsm_x4(r0, r1, r2, r3, bBase + bOff[nt2] + ks);
                b[2 * nt2][0] = r0; b[2 * nt2][1] = r1;
                b[2 * nt2 + 1][0] = r2; b[2 * nt2 + 1][1] = r3;
            }
            #pragma unroll
            for (int mt = 0; mt < 4; ++mt)
                #pragma unroll
                for (int nt = 0; nt < 4; ++nt)
                    mma_16816(c[mt][nt], a[mt][0], a[mt][1], a[mt][2], a[mt][3],
                              b[nt][0], b[nt][1]);
        }

        // loads in the shadow of this iteration's compute; target buffer
        // (kt+3)%4 == (kt-1)%4, whose consumption was ordered before bar1(kt).
        const int pf = kt + STAGES - 1;
        if (pf < KT) load_stage(pf, pf & (STAGES - 1));
        CP_COMMIT();                     // commit every iter (possibly empty group)
    }
    CP_WAIT0();

    // ---- epilogue: direct fp32 stores ----
    const int mwbase = mtile * TILE_M + warp_m * 64;
    const int nwbase = ntile * TILE_N + warp_n * 32;
    const int qrow = lane >> 2;          // 0..7
    const int qcol = (lane & 3) * 2;     // 0,2,4,6
    #pragma unroll
    for (int mt = 0; mt < 4; ++mt) {
        #pragma unroll
        for (int nt = 0; nt < 4; ++nt) {
            const int m0 = mwbase + mt * 16 + qrow;
            const int n0 = nwbase + nt * 8 + qcol;
            float2 v0 = make_float2(c[mt][nt][0], c[mt][nt][1]);
            float2 v1 = make_float2(c[mt][nt][2], c[mt][nt][3]);
            *reinterpret_cast<float2*>(out + (size_t)m0 * N_FEAT + n0) = v0;
            *reinterpret_cast<float2*>(out + (size_t)(m0 + 8) * N_FEAT + n0) = v1;
        }
    }
}

// ============================ launch =======================================
extern "C" void kernel_launch(void* const* d_in, const int* in_sizes, int n_in,
                              void* d_out, int out_size) {
    const float* x       = (const float*)d_in[0];
    const int*   wpacked = (const int*)d_in[1];
    const float* wparams = (const float*)d_in[2];
    float* out = (float*)d_out;

    cudaFuncSetAttribute(gemm_f16_kernel, cudaFuncAttributeMaxDynamicSharedMemorySize,
                         SMEM_BYTES);

    const int n4  = (M_ROWS * K_FEAT) / 4;         // 8,388,608 float4s
    const int npk = (N_FEAT * K_FEAT) / 2;         // 8,388,608 packed int32s
    prologue_kernel<<<4096, 256>>>(reinterpret_cast<const float4*>(x), n4,
                                   wpacked, wparams, npk);

    dim3 grid(N_FEAT / TILE_N, M_ROWS / TILE_M);   // (16, 64)
    gemm_f16_kernel<<<grid, 512, SMEM_BYTES>>>(out);
}